// round 5
// baseline (speedup 1.0000x reference)
#include <cuda_runtime.h>
#include <math.h>

#define PH 512
#define PW 512
#define NCH 32
#define HIDDEN 128
#define ALPHA 1e-4f
#define MAX_CAMS 4096
#define CPB 8
#define MLP_TPB 128

// Per-camera final 4x4 matrices (row-major), float4-aligned.
__device__ float4 g_table[MAX_CAMS * 4];
// Per-camera tri-plane codes: [cam][96], layout [0:32) xy, [32:64) xz, [64:96) yz
__device__ float g_codes[MAX_CAMS * 96];

__device__ __forceinline__ float silu_f(float x) {
    return x / (1.0f + expf(-x));
}

// ---------------------------------------------------------------------------
// Kernel 1: tri-plane sampling. One warp per (cam, plane); lane = channel.
// All lanes share the same (x,y) coords; each lane issues 4 independent LDGs.
// ---------------------------------------------------------------------------
__global__ void __launch_bounds__(256) sample_kernel(
    const float* __restrict__ t,
    const float* __restrict__ pxy,
    const float* __restrict__ pxz,
    const float* __restrict__ pyz,
    int num_cams)
{
    int gwarp = (blockIdx.x * 256 + threadIdx.x) >> 5;
    int lane = threadIdx.x & 31;
    int cam = gwarp / 3;
    int p = gwarp - cam * 3;
    if (cam >= num_cams) return;

    float tx = __ldg(t + cam * 3 + 0);
    float ty = __ldg(t + cam * 3 + 1);
    float tz = __ldg(t + cam * 3 + 2);

    float cx, cy;
    const float* plane;
    if (p == 0)      { plane = pxy; cx = tx; cy = ty; }
    else if (p == 1) { plane = pxz; cx = tx; cy = tz; }
    else             { plane = pyz; cx = ty; cy = tz; }

    // align_corners=True, border padding — matches reference fp32 math
    float x = (cx + 1.0f) * 0.5f * (float)(PW - 1);
    float y = (cy + 1.0f) * 0.5f * (float)(PH - 1);
    float x0f = floorf(x), y0f = floorf(y);
    float wx = x - x0f, wy = y - y0f;
    int x0 = min(max((int)x0f, 0), PW - 1);
    int x1 = min(max((int)x0f + 1, 0), PW - 1);
    int y0 = min(max((int)y0f, 0), PH - 1);
    int y1 = min(max((int)y0f + 1, 0), PH - 1);

    const float* pc = plane + (size_t)lane * (PH * PW);
    float v00 = __ldg(pc + y0 * PW + x0);
    float v01 = __ldg(pc + y0 * PW + x1);
    float v10 = __ldg(pc + y1 * PW + x0);
    float v11 = __ldg(pc + y1 * PW + x1);

    float r = v00 * (1.0f - wx) * (1.0f - wy)
            + v01 * wx * (1.0f - wy)
            + v10 * (1.0f - wx) * wy
            + v11 * wx * wy;

    g_codes[cam * 96 + p * 32 + lane] = r;   // coalesced 128B per warp
}

// ---------------------------------------------------------------------------
// Kernel 2: MLP + Rodrigues + c2w @ init_c2w. 8 cams per 128-thread block.
// ---------------------------------------------------------------------------
__global__ void __launch_bounds__(MLP_TPB) mlp_kernel(
    const float* __restrict__ t,
    const float* __restrict__ w1, const float* __restrict__ b1,
    const float* __restrict__ w2, const float* __restrict__ b2,
    const float* __restrict__ w3, const float* __restrict__ b3,
    const float* __restrict__ init_c2w,
    int num_cams)
{
    int cam0 = blockIdx.x * CPB;
    int tid = threadIdx.x;

    __shared__ float s_ts[CPB][4];
    __shared__ float s_codes[CPB][96];
    __shared__ float s_h1[CPB][HIDDEN];
    __shared__ float s_h2[CPB][HIDDEN];
    __shared__ float s_part[CPB * 3][2];
    __shared__ float s_rot[CPB][3];

    if (tid < CPB * 3) {
        int c = tid / 3, a = tid % 3;
        int cam = cam0 + c;
        s_ts[c][a] = (cam < num_cams) ? __ldg(t + cam * 3 + a) : 0.0f;
    }
    // Load codes: CPB*96 = 768 contiguous floats = 192 float4 loads.
    {
        int n4 = CPB * 96 / 4;                 // 192
        const float4* src = (const float4*)(g_codes + (size_t)cam0 * 96);
        float* dst = &s_codes[0][0];
        if (tid < n4) {
            int last_cam = cam0 + (tid * 4) / 96;
            float4 v = (last_cam < num_cams) ? __ldg(src + tid)
                                             : make_float4(0.f, 0.f, 0.f, 0.f);
            ((float4*)dst)[tid] = v;
        }
    }
    __syncthreads();

    // Layer 1: codes(96) @ w1(96,128) + b1 -> silu
    {
        float acc[CPB];
        float bv = __ldg(b1 + tid);
        #pragma unroll
        for (int c = 0; c < CPB; c++) acc[c] = bv;
        #pragma unroll 8
        for (int k = 0; k < 96; k++) {
            float w = __ldg(w1 + k * HIDDEN + tid);
            #pragma unroll
            for (int c = 0; c < CPB; c++) acc[c] = fmaf(s_codes[c][k], w, acc[c]);
        }
        #pragma unroll
        for (int c = 0; c < CPB; c++) s_h1[c][tid] = silu_f(acc[c]);
    }
    __syncthreads();

    // Layer 2: h1(128) @ w2(128,128) + b2 -> silu
    {
        float acc[CPB];
        float bv = __ldg(b2 + tid);
        #pragma unroll
        for (int c = 0; c < CPB; c++) acc[c] = bv;
        #pragma unroll 8
        for (int k = 0; k < HIDDEN; k++) {
            float w = __ldg(w2 + k * HIDDEN + tid);
            #pragma unroll
            for (int c = 0; c < CPB; c++) acc[c] = fmaf(s_h1[c][k], w, acc[c]);
        }
        #pragma unroll
        for (int c = 0; c < CPB; c++) s_h2[c][tid] = silu_f(acc[c]);
    }
    __syncthreads();

    // Layer 3: h2(128) @ w3(128,3) + b3, * ALPHA. 24 outputs x 2 k-halves.
    if (tid < CPB * 3 * 2) {
        int out_idx = tid >> 1;
        int half = tid & 1;
        int c = out_idx / 3, m = out_idx % 3;
        float acc = 0.0f;
        int k0 = half * 64;
        #pragma unroll 8
        for (int k = k0; k < k0 + 64; k++)
            acc = fmaf(s_h2[c][k], __ldg(w3 + k * 3 + m), acc);
        s_part[out_idx][half] = acc;
    }
    __syncthreads();
    if (tid < CPB * 3) {
        int c = tid / 3, m = tid % 3;
        s_rot[c][m] = (s_part[tid][0] + s_part[tid][1] + __ldg(b3 + m)) * ALPHA;
    }
    __syncthreads();

    // Rodrigues + [R|t;0001] @ init_c2w, one camera per thread.
    if (tid < CPB) {
        int cam = cam0 + tid;
        if (cam < num_cams) {
            float rx = s_rot[tid][0], ry = s_rot[tid][1], rz = s_rot[tid][2];
            float th2 = rx * rx + ry * ry + rz * rz;
            float th = sqrtf(th2);
            float A = sinf(th) / (th + 1e-10f);
            float B = (1.0f - cosf(th)) / (th2 + 1e-10f);
            float R00 = 1.0f - B * (ry * ry + rz * rz);
            float R01 = -A * rz + B * (rx * ry);
            float R02 =  A * ry + B * (rx * rz);
            float R10 =  A * rz + B * (rx * ry);
            float R11 = 1.0f - B * (rx * rx + rz * rz);
            float R12 = -A * rx + B * (ry * rz);
            float R20 = -A * ry + B * (rx * rz);
            float R21 =  A * rx + B * (ry * rz);
            float R22 = 1.0f - B * (rx * rx + ry * ry);

            float tx = s_ts[tid][0], ty = s_ts[tid][1], tz = s_ts[tid][2];
            float C[3][4] = {
                {R00, R01, R02, tx},
                {R10, R11, R12, ty},
                {R20, R21, R22, tz}
            };
            const float* M = init_c2w + (size_t)cam * 16;
            float* o = (float*)(g_table + cam * 4);
            #pragma unroll
            for (int i = 0; i < 3; i++) {
                #pragma unroll
                for (int j = 0; j < 4; j++) {
                    o[i * 4 + j] = C[i][0] * __ldg(M + j)
                                 + C[i][1] * __ldg(M + 4 + j)
                                 + C[i][2] * __ldg(M + 8 + j)
                                 + C[i][3] * __ldg(M + 12 + j);
                }
            }
            o[12] = __ldg(M + 12);
            o[13] = __ldg(M + 13);
            o[14] = __ldg(M + 14);
            o[15] = __ldg(M + 15);
        }
    }
}

// ---------------------------------------------------------------------------
// Kernel 3: scatter with 4-way ILP. Each thread handles 4 strided float4
// slots: batch 4 cam_id loads, then 4 independent table loads, then 4 stores.
// ---------------------------------------------------------------------------
__global__ void __launch_bounds__(256) scatter_kernel(
    const int* __restrict__ cam_id,
    float4* __restrict__ out,
    int n4, int stride)
{
    int i = blockIdx.x * 256 + threadIdx.x;
    int idx0 = i;
    int idx1 = i + stride;
    int idx2 = i + 2 * stride;
    int idx3 = i + 3 * stride;

    bool p0 = idx0 < n4, p1 = idx1 < n4, p2 = idx2 < n4, p3 = idx3 < n4;

    int c0 = p0 ? __ldg(cam_id + (idx0 >> 2)) : 0;
    int c1 = p1 ? __ldg(cam_id + (idx1 >> 2)) : 0;
    int c2 = p2 ? __ldg(cam_id + (idx2 >> 2)) : 0;
    int c3 = p3 ? __ldg(cam_id + (idx3 >> 2)) : 0;

    float4 v0 = __ldg(&g_table[c0 * 4 + (idx0 & 3)]);
    float4 v1 = __ldg(&g_table[c1 * 4 + (idx1 & 3)]);
    float4 v2 = __ldg(&g_table[c2 * 4 + (idx2 & 3)]);
    float4 v3 = __ldg(&g_table[c3 * 4 + (idx3 & 3)]);

    if (p0) out[idx0] = v0;
    if (p1) out[idx1] = v1;
    if (p2) out[idx2] = v2;
    if (p3) out[idx3] = v3;
}

extern "C" void kernel_launch(void* const* d_in, const int* in_sizes, int n_in,
                              void* d_out, int out_size) {
    const int*   cam_id   = (const int*)d_in[0];
    const float* t        = (const float*)d_in[1];
    const float* pxy      = (const float*)d_in[2];
    const float* pxz      = (const float*)d_in[3];
    const float* pyz      = (const float*)d_in[4];
    const float* w1       = (const float*)d_in[5];
    const float* b1       = (const float*)d_in[6];
    const float* w2       = (const float*)d_in[7];
    const float* b2       = (const float*)d_in[8];
    const float* w3       = (const float*)d_in[9];
    const float* b3       = (const float*)d_in[10];
    const float* init_c2w = (const float*)d_in[11];

    int n_rays = in_sizes[0];
    int num_cams = in_sizes[1] / 3;
    if (num_cams > MAX_CAMS) num_cams = MAX_CAMS;

    // Kernel 1: sampling. One warp per (cam, plane).
    int n_warps = num_cams * 3;
    int nblk_s = (n_warps * 32 + 255) / 256;
    sample_kernel<<<nblk_s, 256>>>(t, pxy, pxz, pyz, num_cams);

    // Kernel 2: MLP + pose.
    int nblk_m = (num_cams + CPB - 1) / CPB;
    mlp_kernel<<<nblk_m, MLP_TPB>>>(t, w1, b1, w2, b2, w3, b3, init_c2w,
                                    num_cams);

    // Kernel 3: scatter with 4-way ILP.
    int n4 = n_rays * 4;
    int stride = (n4 + 3) / 4;
    int nblk_sc = (stride + 255) / 256;
    scatter_kernel<<<nblk_sc, 256>>>(cam_id, (float4*)d_out, n4, stride);
}

// round 6
// speedup vs baseline: 1.2819x; 1.2819x over previous
#include <cuda_runtime.h>
#include <math.h>

#define PH 512
#define PW 512
#define HIDDEN 128
#define ALPHA 1e-4f
#define MAX_CAMS 4096
#define CPB 8
#define TPB 256

// Per-camera final 4x4 matrices (row-major), float4-aligned.
__device__ float4 g_table[MAX_CAMS * 4];

__device__ __forceinline__ float silu_f(float x) {
    return x / (1.0f + expf(-x));
}

__device__ __forceinline__ unsigned long long pack2(float w) {
    unsigned long long r;
    asm("mov.b64 %0, {%1, %1};" : "=l"(r) : "f"(w));
    return r;
}
__device__ __forceinline__ void fma2(unsigned long long& acc,
                                     unsigned long long a,
                                     unsigned long long b) {
    asm("fma.rn.f32x2 %0, %1, %2, %3;" : "=l"(acc) : "l"(a), "l"(b), "l"(acc));
}
__device__ __forceinline__ float lo32(unsigned long long v) {
    return __uint_as_float((unsigned)(v & 0xffffffffull));
}
__device__ __forceinline__ float hi32(unsigned long long v) {
    return __uint_as_float((unsigned)(v >> 32));
}

// ---------------------------------------------------------------------------
// Fused kernel: tri-plane sampling + MLP + Rodrigues + c2w @ init_c2w.
// 8 cams per 256-thread block.
//   Phase A: 24 (cam,plane) sampling tasks, one per warp-task (8 warps x 3).
//   Phase B: MLP with k-split across the two 128-thread halves, f32x2 packed.
// ---------------------------------------------------------------------------
__global__ void __launch_bounds__(TPB) cam_kernel(
    const float* __restrict__ t,
    const float* __restrict__ pxy,
    const float* __restrict__ pxz,
    const float* __restrict__ pyz,
    const float* __restrict__ w1, const float* __restrict__ b1,
    const float* __restrict__ w2, const float* __restrict__ b2,
    const float* __restrict__ w3, const float* __restrict__ b3,
    const float* __restrict__ init_c2w,
    int num_cams)
{
    int cam0 = blockIdx.x * CPB;
    int tid = threadIdx.x;
    int warp = tid >> 5;
    int lane = tid & 31;
    int half = tid >> 7;         // k-split half
    int htid = tid & 127;        // hidden unit index

    __shared__ float s_ts[CPB][4];
    __shared__ float s_codes[96][CPB];           // [k][cam], cam-minor for f32x2
    __shared__ unsigned long long s_p1[2][HIDDEN][4];  // layer1 partials (half,hid,campair)
    __shared__ float s_h1[HIDDEN][CPB];
    __shared__ unsigned long long s_p2[2][HIDDEN][4];
    __shared__ float s_h2[HIDDEN][CPB];
    __shared__ float s_part[CPB * 3][2];
    __shared__ float s_rot[CPB][3];

    if (tid < CPB * 3) {
        int c = tid / 3, a = tid % 3;
        int cam = cam0 + c;
        s_ts[c][a] = (cam < num_cams) ? __ldg(t + cam * 3 + a) : 0.0f;
    }
    __syncthreads();

    // ---- Phase A: sampling. Tasks 0..23: cam=task/3, plane=task%3. ----
    #pragma unroll
    for (int i = 0; i < 3; i++) {
        int task = warp * 3 + i;
        int c = task / 3;
        int p = task - c * 3;
        int cam = cam0 + c;
        float cx, cy;
        const float* plane;
        if (p == 0)      { plane = pxy; cx = s_ts[c][0]; cy = s_ts[c][1]; }
        else if (p == 1) { plane = pxz; cx = s_ts[c][0]; cy = s_ts[c][2]; }
        else             { plane = pyz; cx = s_ts[c][1]; cy = s_ts[c][2]; }

        float x = (cx + 1.0f) * 0.5f * (float)(PW - 1);
        float y = (cy + 1.0f) * 0.5f * (float)(PH - 1);
        float x0f = floorf(x), y0f = floorf(y);
        float wx = x - x0f, wy = y - y0f;
        int x0 = min(max((int)x0f, 0), PW - 1);
        int x1 = min(max((int)x0f + 1, 0), PW - 1);
        int y0 = min(max((int)y0f, 0), PH - 1);
        int y1 = min(max((int)y0f + 1, 0), PH - 1);

        const float* pc = plane + (size_t)lane * (PH * PW);
        float v00 = __ldg(pc + y0 * PW + x0);
        float v01 = __ldg(pc + y0 * PW + x1);
        float v10 = __ldg(pc + y1 * PW + x0);
        float v11 = __ldg(pc + y1 * PW + x1);

        float r = v00 * (1.0f - wx) * (1.0f - wy)
                + v01 * wx * (1.0f - wy)
                + v10 * (1.0f - wx) * wy
                + v11 * wx * wy;
        if (cam < num_cams) s_codes[p * 32 + lane][c] = r;
        else                s_codes[p * 32 + lane][c] = 0.0f;
    }
    __syncthreads();

    // ---- Layer 1: codes(96) @ w1(96,128), k-split 48/48, f32x2 packed ----
    {
        unsigned long long acc[4] = {0ull, 0ull, 0ull, 0ull};
        int k0 = half * 48;
        #pragma unroll 4
        for (int k = k0; k < k0 + 48; k++) {
            float w = __ldg(w1 + k * HIDDEN + htid);
            unsigned long long wp = pack2(w);
            const ulonglong2* row = (const ulonglong2*)&s_codes[k][0];
            ulonglong2 q0 = row[0];
            ulonglong2 q1 = row[1];
            fma2(acc[0], q0.x, wp);
            fma2(acc[1], q0.y, wp);
            fma2(acc[2], q1.x, wp);
            fma2(acc[3], q1.y, wp);
        }
        #pragma unroll
        for (int j = 0; j < 4; j++) s_p1[half][htid][j] = acc[j];
    }
    __syncthreads();
    // combine + bias + silu -> s_h1[hid][cam]
    {
        #pragma unroll
        for (int j = 0; j < 2; j++) {
            int pairidx = tid + 256 * j;     // 0..511
            int hid = pairidx >> 2;
            int pr = pairidx & 3;
            float bv = __ldg(b1 + hid);
            unsigned long long a = s_p1[0][hid][pr];
            unsigned long long b = s_p1[1][hid][pr];
            float v0 = lo32(a) + lo32(b) + bv;
            float v1 = hi32(a) + hi32(b) + bv;
            s_h1[hid][pr * 2 + 0] = silu_f(v0);
            s_h1[hid][pr * 2 + 1] = silu_f(v1);
        }
    }
    __syncthreads();

    // ---- Layer 2: h1(128) @ w2(128,128), k-split 64/64 ----
    {
        unsigned long long acc[4] = {0ull, 0ull, 0ull, 0ull};
        int k0 = half * 64;
        #pragma unroll 4
        for (int k = k0; k < k0 + 64; k++) {
            float w = __ldg(w2 + k * HIDDEN + htid);
            unsigned long long wp = pack2(w);
            const ulonglong2* row = (const ulonglong2*)&s_h1[k][0];
            ulonglong2 q0 = row[0];
            ulonglong2 q1 = row[1];
            fma2(acc[0], q0.x, wp);
            fma2(acc[1], q0.y, wp);
            fma2(acc[2], q1.x, wp);
            fma2(acc[3], q1.y, wp);
        }
        #pragma unroll
        for (int j = 0; j < 4; j++) s_p2[half][htid][j] = acc[j];
    }
    __syncthreads();
    {
        #pragma unroll
        for (int j = 0; j < 2; j++) {
            int pairidx = tid + 256 * j;
            int hid = pairidx >> 2;
            int pr = pairidx & 3;
            float bv = __ldg(b2 + hid);
            unsigned long long a = s_p2[0][hid][pr];
            unsigned long long b = s_p2[1][hid][pr];
            float v0 = lo32(a) + lo32(b) + bv;
            float v1 = hi32(a) + hi32(b) + bv;
            s_h2[hid][pr * 2 + 0] = silu_f(v0);
            s_h2[hid][pr * 2 + 1] = silu_f(v1);
        }
    }
    __syncthreads();

    // ---- Layer 3: h2(128) @ w3(128,3) + b3, * ALPHA. 48 outs x 2 k-halves ----
    if (tid < CPB * 3 * 2) {
        int out_idx = tid >> 1;
        int h = tid & 1;
        int c = out_idx / 3, m = out_idx % 3;
        float acc = 0.0f;
        int k0 = h * 64;
        #pragma unroll 8
        for (int k = k0; k < k0 + 64; k++)
            acc = fmaf(s_h2[k][c], __ldg(w3 + k * 3 + m), acc);
        s_part[out_idx][h] = acc;
    }
    __syncthreads();
    if (tid < CPB * 3) {
        int c = tid / 3, m = tid % 3;
        s_rot[c][m] = (s_part[tid][0] + s_part[tid][1] + __ldg(b3 + m)) * ALPHA;
    }
    __syncthreads();

    // ---- Rodrigues + [R|t;0001] @ init_c2w, one camera per thread ----
    if (tid < CPB) {
        int cam = cam0 + tid;
        if (cam < num_cams) {
            float rx = s_rot[tid][0], ry = s_rot[tid][1], rz = s_rot[tid][2];
            float th2 = rx * rx + ry * ry + rz * rz;
            float th = sqrtf(th2);
            float A = sinf(th) / (th + 1e-10f);
            float B = (1.0f - cosf(th)) / (th2 + 1e-10f);
            float R00 = 1.0f - B * (ry * ry + rz * rz);
            float R01 = -A * rz + B * (rx * ry);
            float R02 =  A * ry + B * (rx * rz);
            float R10 =  A * rz + B * (rx * ry);
            float R11 = 1.0f - B * (rx * rx + rz * rz);
            float R12 = -A * rx + B * (ry * rz);
            float R20 = -A * ry + B * (rx * rz);
            float R21 =  A * rx + B * (ry * rz);
            float R22 = 1.0f - B * (rx * rx + ry * ry);

            float tx = s_ts[tid][0], ty = s_ts[tid][1], tz = s_ts[tid][2];
            float C[3][4] = {
                {R00, R01, R02, tx},
                {R10, R11, R12, ty},
                {R20, R21, R22, tz}
            };
            const float* M = init_c2w + (size_t)cam * 16;
            float* o = (float*)(g_table + cam * 4);
            #pragma unroll
            for (int i = 0; i < 3; i++) {
                #pragma unroll
                for (int j = 0; j < 4; j++) {
                    o[i * 4 + j] = C[i][0] * __ldg(M + j)
                                 + C[i][1] * __ldg(M + 4 + j)
                                 + C[i][2] * __ldg(M + 8 + j)
                                 + C[i][3] * __ldg(M + 12 + j);
                }
            }
            o[12] = __ldg(M + 12);
            o[13] = __ldg(M + 13);
            o[14] = __ldg(M + 14);
            o[15] = __ldg(M + 15);
        }
    }
}

// ---------------------------------------------------------------------------
// Scatter with 4-way ILP: batch cam_id loads, then table loads, then stores.
// 4 consecutive threads handle one ray -> fully coalesced STG.128.
// ---------------------------------------------------------------------------
__global__ void __launch_bounds__(256) scatter_kernel(
    const int* __restrict__ cam_id,
    float4* __restrict__ out,
    int n4, int stride)
{
    int i = blockIdx.x * 256 + threadIdx.x;
    int idx0 = i;
    int idx1 = i + stride;
    int idx2 = i + 2 * stride;
    int idx3 = i + 3 * stride;

    bool p0 = idx0 < n4, p1 = idx1 < n4, p2 = idx2 < n4, p3 = idx3 < n4;

    int c0 = p0 ? __ldg(cam_id + (idx0 >> 2)) : 0;
    int c1 = p1 ? __ldg(cam_id + (idx1 >> 2)) : 0;
    int c2 = p2 ? __ldg(cam_id + (idx2 >> 2)) : 0;
    int c3 = p3 ? __ldg(cam_id + (idx3 >> 2)) : 0;

    float4 v0 = __ldg(&g_table[c0 * 4 + (idx0 & 3)]);
    float4 v1 = __ldg(&g_table[c1 * 4 + (idx1 & 3)]);
    float4 v2 = __ldg(&g_table[c2 * 4 + (idx2 & 3)]);
    float4 v3 = __ldg(&g_table[c3 * 4 + (idx3 & 3)]);

    if (p0) out[idx0] = v0;
    if (p1) out[idx1] = v1;
    if (p2) out[idx2] = v2;
    if (p3) out[idx3] = v3;
}

extern "C" void kernel_launch(void* const* d_in, const int* in_sizes, int n_in,
                              void* d_out, int out_size) {
    const int*   cam_id   = (const int*)d_in[0];
    const float* t        = (const float*)d_in[1];
    const float* pxy      = (const float*)d_in[2];
    const float* pxz      = (const float*)d_in[3];
    const float* pyz      = (const float*)d_in[4];
    const float* w1       = (const float*)d_in[5];
    const float* b1       = (const float*)d_in[6];
    const float* w2       = (const float*)d_in[7];
    const float* b2       = (const float*)d_in[8];
    const float* w3       = (const float*)d_in[9];
    const float* b3       = (const float*)d_in[10];
    const float* init_c2w = (const float*)d_in[11];

    int n_rays = in_sizes[0];
    int num_cams = in_sizes[1] / 3;
    if (num_cams > MAX_CAMS) num_cams = MAX_CAMS;

    int nblk1 = (num_cams + CPB - 1) / CPB;
    cam_kernel<<<nblk1, TPB>>>(t, pxy, pxz, pyz, w1, b1, w2, b2, w3, b3,
                               init_c2w, num_cams);

    int n4 = n_rays * 4;
    int stride = (n4 + 3) / 4;
    int nblk_sc = (stride + 255) / 256;
    scatter_kernel<<<nblk_sc, 256>>>(cam_id, (float4*)d_out, n4, stride);
}

// round 7
// speedup vs baseline: 1.4359x; 1.1201x over previous
#include <cuda_runtime.h>
#include <math.h>

#define PH 512
#define PW 512
#define HIDDEN 128
#define ALPHA 1e-4f
#define MAX_CAMS 4096
#define CPB 8
#define TPB 256

// Per-camera final 4x4 matrices (row-major), float4-aligned.
__device__ float4 g_table[MAX_CAMS * 4];

__device__ __forceinline__ float silu_f(float x) {
    return x / (1.0f + expf(-x));
}

__device__ __forceinline__ unsigned long long pack2(float w) {
    unsigned long long r;
    asm("mov.b64 %0, {%1, %1};" : "=l"(r) : "f"(w));
    return r;
}
__device__ __forceinline__ void fma2(unsigned long long& acc,
                                     unsigned long long a,
                                     unsigned long long b) {
    asm("fma.rn.f32x2 %0, %1, %2, %3;" : "=l"(acc) : "l"(a), "l"(b), "l"(acc));
}
__device__ __forceinline__ float lo32(unsigned long long v) {
    return __uint_as_float((unsigned)(v & 0xffffffffull));
}
__device__ __forceinline__ float hi32(unsigned long long v) {
    return __uint_as_float((unsigned)(v >> 32));
}

// ---------------------------------------------------------------------------
// Fused kernel: tri-plane sampling + MLP + Rodrigues + c2w @ init_c2w.
// 8 cams per 256-thread block. (unchanged from R6 — correct, sampling-bound)
// ---------------------------------------------------------------------------
__global__ void __launch_bounds__(TPB) cam_kernel(
    const float* __restrict__ t,
    const float* __restrict__ pxy,
    const float* __restrict__ pxz,
    const float* __restrict__ pyz,
    const float* __restrict__ w1, const float* __restrict__ b1,
    const float* __restrict__ w2, const float* __restrict__ b2,
    const float* __restrict__ w3, const float* __restrict__ b3,
    const float* __restrict__ init_c2w,
    int num_cams)
{
    int cam0 = blockIdx.x * CPB;
    int tid = threadIdx.x;
    int warp = tid >> 5;
    int lane = tid & 31;
    int half = tid >> 7;         // k-split half
    int htid = tid & 127;        // hidden unit index

    __shared__ float s_ts[CPB][4];
    __shared__ float s_codes[96][CPB];           // [k][cam], cam-minor for f32x2
    __shared__ unsigned long long s_p1[2][HIDDEN][4];
    __shared__ float s_h1[HIDDEN][CPB];
    __shared__ unsigned long long s_p2[2][HIDDEN][4];
    __shared__ float s_h2[HIDDEN][CPB];
    __shared__ float s_part[CPB * 3][2];
    __shared__ float s_rot[CPB][3];

    if (tid < CPB * 3) {
        int c = tid / 3, a = tid % 3;
        int cam = cam0 + c;
        s_ts[c][a] = (cam < num_cams) ? __ldg(t + cam * 3 + a) : 0.0f;
    }
    __syncthreads();

    // ---- Phase A: sampling. Tasks 0..23: cam=task/3, plane=task%3. ----
    #pragma unroll
    for (int i = 0; i < 3; i++) {
        int task = warp * 3 + i;
        int c = task / 3;
        int p = task - c * 3;
        int cam = cam0 + c;
        float cx, cy;
        const float* plane;
        if (p == 0)      { plane = pxy; cx = s_ts[c][0]; cy = s_ts[c][1]; }
        else if (p == 1) { plane = pxz; cx = s_ts[c][0]; cy = s_ts[c][2]; }
        else             { plane = pyz; cx = s_ts[c][1]; cy = s_ts[c][2]; }

        float x = (cx + 1.0f) * 0.5f * (float)(PW - 1);
        float y = (cy + 1.0f) * 0.5f * (float)(PH - 1);
        float x0f = floorf(x), y0f = floorf(y);
        float wx = x - x0f, wy = y - y0f;
        int x0 = min(max((int)x0f, 0), PW - 1);
        int x1 = min(max((int)x0f + 1, 0), PW - 1);
        int y0 = min(max((int)y0f, 0), PH - 1);
        int y1 = min(max((int)y0f + 1, 0), PH - 1);

        const float* pc = plane + (size_t)lane * (PH * PW);
        float v00 = __ldg(pc + y0 * PW + x0);
        float v01 = __ldg(pc + y0 * PW + x1);
        float v10 = __ldg(pc + y1 * PW + x0);
        float v11 = __ldg(pc + y1 * PW + x1);

        float r = v00 * (1.0f - wx) * (1.0f - wy)
                + v01 * wx * (1.0f - wy)
                + v10 * (1.0f - wx) * wy
                + v11 * wx * wy;
        if (cam < num_cams) s_codes[p * 32 + lane][c] = r;
        else                s_codes[p * 32 + lane][c] = 0.0f;
    }
    __syncthreads();

    // ---- Layer 1: codes(96) @ w1(96,128), k-split 48/48, f32x2 packed ----
    {
        unsigned long long acc[4] = {0ull, 0ull, 0ull, 0ull};
        int k0 = half * 48;
        #pragma unroll 4
        for (int k = k0; k < k0 + 48; k++) {
            float w = __ldg(w1 + k * HIDDEN + htid);
            unsigned long long wp = pack2(w);
            const ulonglong2* row = (const ulonglong2*)&s_codes[k][0];
            ulonglong2 q0 = row[0];
            ulonglong2 q1 = row[1];
            fma2(acc[0], q0.x, wp);
            fma2(acc[1], q0.y, wp);
            fma2(acc[2], q1.x, wp);
            fma2(acc[3], q1.y, wp);
        }
        #pragma unroll
        for (int j = 0; j < 4; j++) s_p1[half][htid][j] = acc[j];
    }
    __syncthreads();
    {
        #pragma unroll
        for (int j = 0; j < 2; j++) {
            int pairidx = tid + 256 * j;     // 0..511
            int hid = pairidx >> 2;
            int pr = pairidx & 3;
            float bv = __ldg(b1 + hid);
            unsigned long long a = s_p1[0][hid][pr];
            unsigned long long b = s_p1[1][hid][pr];
            float v0 = lo32(a) + lo32(b) + bv;
            float v1 = hi32(a) + hi32(b) + bv;
            s_h1[hid][pr * 2 + 0] = silu_f(v0);
            s_h1[hid][pr * 2 + 1] = silu_f(v1);
        }
    }
    __syncthreads();

    // ---- Layer 2: h1(128) @ w2(128,128), k-split 64/64 ----
    {
        unsigned long long acc[4] = {0ull, 0ull, 0ull, 0ull};
        int k0 = half * 64;
        #pragma unroll 4
        for (int k = k0; k < k0 + 64; k++) {
            float w = __ldg(w2 + k * HIDDEN + htid);
            unsigned long long wp = pack2(w);
            const ulonglong2* row = (const ulonglong2*)&s_h1[k][0];
            ulonglong2 q0 = row[0];
            ulonglong2 q1 = row[1];
            fma2(acc[0], q0.x, wp);
            fma2(acc[1], q0.y, wp);
            fma2(acc[2], q1.x, wp);
            fma2(acc[3], q1.y, wp);
        }
        #pragma unroll
        for (int j = 0; j < 4; j++) s_p2[half][htid][j] = acc[j];
    }
    __syncthreads();
    {
        #pragma unroll
        for (int j = 0; j < 2; j++) {
            int pairidx = tid + 256 * j;
            int hid = pairidx >> 2;
            int pr = pairidx & 3;
            float bv = __ldg(b2 + hid);
            unsigned long long a = s_p2[0][hid][pr];
            unsigned long long b = s_p2[1][hid][pr];
            float v0 = lo32(a) + lo32(b) + bv;
            float v1 = hi32(a) + hi32(b) + bv;
            s_h2[hid][pr * 2 + 0] = silu_f(v0);
            s_h2[hid][pr * 2 + 1] = silu_f(v1);
        }
    }
    __syncthreads();

    // ---- Layer 3: h2(128) @ w3(128,3) + b3, * ALPHA. 48 outs x 2 k-halves ----
    if (tid < CPB * 3 * 2) {
        int out_idx = tid >> 1;
        int h = tid & 1;
        int c = out_idx / 3, m = out_idx % 3;
        float acc = 0.0f;
        int k0 = h * 64;
        #pragma unroll 8
        for (int k = k0; k < k0 + 64; k++)
            acc = fmaf(s_h2[k][c], __ldg(w3 + k * 3 + m), acc);
        s_part[out_idx][h] = acc;
    }
    __syncthreads();
    if (tid < CPB * 3) {
        int c = tid / 3, m = tid % 3;
        s_rot[c][m] = (s_part[tid][0] + s_part[tid][1] + __ldg(b3 + m)) * ALPHA;
    }
    __syncthreads();

    // ---- Rodrigues + [R|t;0001] @ init_c2w, one camera per thread ----
    if (tid < CPB) {
        int cam = cam0 + tid;
        if (cam < num_cams) {
            float rx = s_rot[tid][0], ry = s_rot[tid][1], rz = s_rot[tid][2];
            float th2 = rx * rx + ry * ry + rz * rz;
            float th = sqrtf(th2);
            float A = sinf(th) / (th + 1e-10f);
            float B = (1.0f - cosf(th)) / (th2 + 1e-10f);
            float R00 = 1.0f - B * (ry * ry + rz * rz);
            float R01 = -A * rz + B * (rx * ry);
            float R02 =  A * ry + B * (rx * rz);
            float R10 =  A * rz + B * (rx * ry);
            float R11 = 1.0f - B * (rx * rx + rz * rz);
            float R12 = -A * rx + B * (ry * rz);
            float R20 = -A * ry + B * (rx * rz);
            float R21 =  A * rx + B * (ry * rz);
            float R22 = 1.0f - B * (rx * rx + ry * ry);

            float tx = s_ts[tid][0], ty = s_ts[tid][1], tz = s_ts[tid][2];
            float C[3][4] = {
                {R00, R01, R02, tx},
                {R10, R11, R12, ty},
                {R20, R21, R22, tz}
            };
            const float* M = init_c2w + (size_t)cam * 16;
            float* o = (float*)(g_table + cam * 4);
            #pragma unroll
            for (int i = 0; i < 3; i++) {
                #pragma unroll
                for (int j = 0; j < 4; j++) {
                    o[i * 4 + j] = C[i][0] * __ldg(M + j)
                                 + C[i][1] * __ldg(M + 4 + j)
                                 + C[i][2] * __ldg(M + 8 + j)
                                 + C[i][3] * __ldg(M + 12 + j);
                }
            }
            o[12] = __ldg(M + 12);
            o[13] = __ldg(M + 13);
            o[14] = __ldg(M + 14);
            o[15] = __ldg(M + 15);
        }
    }
}

// ---------------------------------------------------------------------------
// Scatter with 8-way ILP + streaming (evict-first) output stores.
// Batched: 8 cam_id loads -> 8 independent table gathers -> 8 stores.
// __stcs keeps the 33.5MB output stream from evicting the L2-resident planes
// (100MB) and table, so the next replay's sampling hits L2 instead of DRAM.
// ---------------------------------------------------------------------------
#define SC_ILP 8
__global__ void __launch_bounds__(256) scatter_kernel(
    const int* __restrict__ cam_id,
    float4* __restrict__ out,
    int n4, int stride)
{
    int i = blockIdx.x * 256 + threadIdx.x;

    int idx[SC_ILP];
    int cid[SC_ILP];
    float4 v[SC_ILP];
    bool pred[SC_ILP];

    #pragma unroll
    for (int j = 0; j < SC_ILP; j++) {
        idx[j] = i + j * stride;
        pred[j] = idx[j] < n4;
        cid[j] = pred[j] ? __ldg(cam_id + (idx[j] >> 2)) : 0;
    }
    #pragma unroll
    for (int j = 0; j < SC_ILP; j++) {
        v[j] = __ldg(&g_table[cid[j] * 4 + (idx[j] & 3)]);
    }
    #pragma unroll
    for (int j = 0; j < SC_ILP; j++) {
        if (pred[j]) __stcs(&out[idx[j]], v[j]);
    }
}

extern "C" void kernel_launch(void* const* d_in, const int* in_sizes, int n_in,
                              void* d_out, int out_size) {
    const int*   cam_id   = (const int*)d_in[0];
    const float* t        = (const float*)d_in[1];
    const float* pxy      = (const float*)d_in[2];
    const float* pxz      = (const float*)d_in[3];
    const float* pyz      = (const float*)d_in[4];
    const float* w1       = (const float*)d_in[5];
    const float* b1       = (const float*)d_in[6];
    const float* w2       = (const float*)d_in[7];
    const float* b2       = (const float*)d_in[8];
    const float* w3       = (const float*)d_in[9];
    const float* b3       = (const float*)d_in[10];
    const float* init_c2w = (const float*)d_in[11];

    int n_rays = in_sizes[0];
    int num_cams = in_sizes[1] / 3;
    if (num_cams > MAX_CAMS) num_cams = MAX_CAMS;

    int nblk1 = (num_cams + CPB - 1) / CPB;
    cam_kernel<<<nblk1, TPB>>>(t, pxy, pxz, pyz, w1, b1, w2, b2, w3, b3,
                               init_c2w, num_cams);

    int n4 = n_rays * 4;
    int stride = (n4 + SC_ILP - 1) / SC_ILP;
    int nblk_sc = (stride + 255) / 256;
    scatter_kernel<<<nblk_sc, 256>>>(cam_id, (float4*)d_out, n4, stride);
}